// round 12
// baseline (speedup 1.0000x reference)
#include <cuda_runtime.h>
#include <cuda_bf16.h>
#include <math.h>
#include <stdint.h>

// Problem constants
#define BB 4
#define NN 2048
#define DD 512
#define HH 8
#define DK 64
#define FFN 2048
#define MROWS (BB*NN)          // 8192

// ---------------- scratch (device globals; allocation-free) ----------------
__device__ float g_xn [MROWS*DD];
__device__ float g_q  [MROWS*DD];            // fp32 (B,H,N,DK)
__device__ __nv_bfloat16 g_kb[MROWS*DD];     // bf16 (B,H,N,DK)
__device__ __nv_bfloat16 g_vb[MROWS*DD];     // bf16 (B,H,N,DK)
__device__ float g_att[MROWS*DD];            // (B,N,D)
__device__ float g_x2 [MROWS*DD];
__device__ float g_h  [MROWS*DD];
__device__ float g_act[MROWS*FFN];
__device__ unsigned short g_idx[(size_t)MROWS*NN];
__device__ int    g_cnt[MROWS];
__device__ int    g_maskmode;
__device__ double g_invf[32];

// ---------------- mask dtype probe -----------------------------------------
__global__ void probe_mask_kernel(const unsigned char* __restrict__ m) {
    __shared__ int ok;
    if (threadIdx.x == 0) ok = 1;
    __syncthreads();
    int bad = 0;
    for (int i = threadIdx.x; i < NN; i += blockDim.x)
        if (m[(size_t)i * (NN + 1)] == 0) bad = 1;
    if (bad) atomicAnd(&ok, 0);
    __syncthreads();
    if (threadIdx.x == 0) g_maskmode = ok ? 0 : 1;
}

// ---------------- build compact index lists (1 warp per query row) ---------
__global__ __launch_bounds__(256) void build_idx_kernel(const unsigned char* __restrict__ mask) {
    int warp = threadIdx.x >> 5;
    int lane = threadIdx.x & 31;
    int row = blockIdx.x * 8 + warp;
    if (row >= MROWS) return;
    int mode = g_maskmode;
    const unsigned char* m8 = mask + (size_t)row * NN;
    const unsigned int* m32 = ((const unsigned int*)mask) + (size_t)row * NN;
    unsigned short* dst = g_idx + (size_t)row * NN;
    int cnt = 0;
    for (int j0 = 0; j0 < NN; j0 += 32) {
        int on = mode == 0 ? (m8[j0 + lane] != 0) : (m32[j0 + lane] != 0u);
        unsigned bal = __ballot_sync(0xffffffffu, on);
        int pre = __popc(bal & ((1u << lane) - 1u));
        if (on) dst[cnt + pre] = (unsigned short)(j0 + lane);
        cnt += __popc(bal);
    }
    if (lane == 0) g_cnt[row] = cnt;
}

// ---------------- RoPE frequency table -------------------------------------
__global__ void rope_init_kernel() {
    int i = threadIdx.x;
    if (i < 32)
        g_invf[i] = exp2(-((double)(2 * i) / 64.0) * 13.287712379549448);
}

// ---------------- LayerNorm -------------------------------------------------
__global__ __launch_bounds__(128) void ln_kernel(const float* __restrict__ x,
                                                 const float* __restrict__ g,
                                                 const float* __restrict__ b,
                                                 float* __restrict__ out) {
    int row = blockIdx.x;
    int t = threadIdx.x;
    const float4* xr = (const float4*)(x + (size_t)row * DD);
    float4 v = xr[t];
    float s  = v.x + v.y + v.z + v.w;
    float s2 = fmaf(v.x, v.x, fmaf(v.y, v.y, fmaf(v.z, v.z, v.w * v.w)));
    #pragma unroll
    for (int off = 16; off > 0; off >>= 1) {
        s  += __shfl_xor_sync(0xffffffffu, s,  off);
        s2 += __shfl_xor_sync(0xffffffffu, s2, off);
    }
    __shared__ float sh[8];
    int w = t >> 5;
    if ((t & 31) == 0) { sh[w] = s; sh[4 + w] = s2; }
    __syncthreads();
    float ts  = sh[0] + sh[1] + sh[2] + sh[3];
    float ts2 = sh[4] + sh[5] + sh[6] + sh[7];
    float mean = ts * (1.0f / DD);
    float var  = ts2 * (1.0f / DD) - mean * mean;
    float inv  = rsqrtf(var + 1e-5f);
    float4 gv = ((const float4*)g)[t];
    float4 bv = ((const float4*)b)[t];
    float4 o;
    o.x = (v.x - mean) * inv * gv.x + bv.x;
    o.y = (v.y - mean) * inv * gv.y + bv.y;
    o.z = (v.z - mean) * inv * gv.z + bv.z;
    o.w = (v.w - mean) * inv * gv.w + bv.w;
    ((float4*)(out + (size_t)row * DD))[t] = o;
}

// ---------------- tf32 helpers ---------------------------------------------
__device__ __forceinline__ uint32_t f2tf(float f) {
    uint32_t u;
    asm("cvt.rna.tf32.f32 %0, %1;" : "=r"(u) : "f"(f));
    return u;
}
__device__ __forceinline__ void mma_tf32(float* d, const uint32_t* a, const uint32_t* b) {
    asm volatile("mma.sync.aligned.m16n8k8.row.col.f32.tf32.tf32.f32 "
                 "{%0,%1,%2,%3}, {%4,%5,%6,%7}, {%8,%9}, {%0,%1,%2,%3};"
                 : "+f"(d[0]), "+f"(d[1]), "+f"(d[2]), "+f"(d[3])
                 : "r"(a[0]), "r"(a[1]), "r"(a[2]), "r"(a[3]),
                   "r"(b[0]), "r"(b[1]));
}

// ============== shared GEMM mainloop (tf32, double-buffered) ================
// Computes acc[2][8][4] for a 128x128 tile: A[m0:m0+128, :K] @ B[:K, n0:n0+128].
struct GemmCore {
    uint32_t (*As)[16][136];
    uint32_t (*Bs)[16][136];
};

#define GEMM_MAINLOOP(A_, B_, K_, Nn_, m0_, n0_, acc_)                          \
    {                                                                           \
        int ar = tid >> 1;                                                      \
        int af = (tid & 1) * 2;                                                 \
        int bk = tid >> 4;                                                      \
        int bn = (tid & 15) * 8;                                                \
        const float* Aptr = (A_) + (size_t)((m0_) + ar) * (K_) + af * 4;        \
        const float* Bptr = (B_) + (size_t)bk * (Nn_) + (n0_) + bn;             \
        float4 ga0 = *(const float4*)(Aptr);                                    \
        float4 ga1 = *(const float4*)(Aptr + 4);                                \
        float4 gb0 = *(const float4*)(Bptr);                                    \
        float4 gb1 = *(const float4*)(Bptr + 4);                                \
        As[0][af * 4 + 0][ar] = f2tf(ga0.x); As[0][af * 4 + 1][ar] = f2tf(ga0.y);\
        As[0][af * 4 + 2][ar] = f2tf(ga0.z); As[0][af * 4 + 3][ar] = f2tf(ga0.w);\
        As[0][af * 4 + 4][ar] = f2tf(ga1.x); As[0][af * 4 + 5][ar] = f2tf(ga1.y);\
        As[0][af * 4 + 6][ar] = f2tf(ga1.z); As[0][af * 4 + 7][ar] = f2tf(ga1.w);\
        {                                                                       \
            uint4 u0, u1;                                                       \
            u0.x = f2tf(gb0.x); u0.y = f2tf(gb0.y);                             \
            u0.z = f2tf(gb0.z); u0.w = f2tf(gb0.w);                             \
            u1.x = f2tf(gb1.x); u1.y = f2tf(gb1.y);                             \
            u1.z = f2tf(gb1.z); u1.w = f2tf(gb1.w);                             \
            *(uint4*)&Bs[0][bk][bn] = u0;                                       \
            *(uint4*)&Bs[0][bk][bn + 4] = u1;                                   \
        }                                                                       \
        __syncthreads();                                                        \
        int cur = 0;                                                            \
        for (int k0 = 0;;) {                                                    \
            int kn = k0 + 16;                                                   \
            bool more = kn < (K_);                                              \
            if (more) {                                                         \
                ga0 = *(const float4*)(Aptr + kn);                              \
                ga1 = *(const float4*)(Aptr + kn + 4);                          \
                gb0 = *(const float4*)(Bptr + (size_t)kn * (Nn_));              \
                gb1 = *(const float4*)(Bptr + (size_t)kn * (Nn_) + 4);          \
            }                                                                   \
            _Pragma("unroll")                                                   \
            for (int kk = 0; kk < 16; kk += 8) {                                \
                uint32_t a[2][4];                                               \
                _Pragma("unroll")                                               \
                for (int mt = 0; mt < 2; mt++) {                                \
                    int m = wm + mt * 16 + g;                                   \
                    a[mt][0] = As[cur][kk + t4][m];                             \
                    a[mt][1] = As[cur][kk + t4][m + 8];                         \
                    a[mt][2] = As[cur][kk + t4 + 4][m];                         \
                    a[mt][3] = As[cur][kk + t4 + 4][m + 8];                     \
                }                                                               \
                uint32_t b[8][2];                                               \
                _Pragma("unroll")                                               \
                for (int nt = 0; nt < 8; nt++) {                                \
                    int n = wn + nt * 8 + g;                                    \
                    b[nt][0] = Bs[cur][kk + t4][n];                             \
                    b[nt][1] = Bs[cur][kk + t4 + 4][n];                         \
                }                                                               \
                _Pragma("unroll")                                               \
                for (int mt = 0; mt < 2; mt++)                                  \
                    _Pragma("unroll")                                           \
                    for (int nt = 0; nt < 8; nt++)                              \
                        mma_tf32(acc_[mt][nt], a[mt], b[nt]);                   \
            }                                                                   \
            if (!more) break;                                                   \
            int nxt = cur ^ 1;                                                  \
            As[nxt][af * 4 + 0][ar] = f2tf(ga0.x);                              \
            As[nxt][af * 4 + 1][ar] = f2tf(ga0.y);                              \
            As[nxt][af * 4 + 2][ar] = f2tf(ga0.z);                              \
            As[nxt][af * 4 + 3][ar] = f2tf(ga0.w);                              \
            As[nxt][af * 4 + 4][ar] = f2tf(ga1.x);                              \
            As[nxt][af * 4 + 5][ar] = f2tf(ga1.y);                              \
            As[nxt][af * 4 + 6][ar] = f2tf(ga1.z);                              \
            As[nxt][af * 4 + 7][ar] = f2tf(ga1.w);                              \
            {                                                                   \
                uint4 u0, u1;                                                   \
                u0.x = f2tf(gb0.x); u0.y = f2tf(gb0.y);                         \
                u0.z = f2tf(gb0.z); u0.w = f2tf(gb0.w);                         \
                u1.x = f2tf(gb1.x); u1.y = f2tf(gb1.y);                         \
                u1.z = f2tf(gb1.z); u1.w = f2tf(gb1.w);                         \
                *(uint4*)&Bs[nxt][bk][bn] = u0;                                 \
                *(uint4*)&Bs[nxt][bk][bn + 4] = u1;                             \
            }                                                                   \
            __syncthreads();                                                    \
            cur = nxt;                                                          \
            k0 = kn;                                                            \
        }                                                                       \
    }

// ---------------- generic GEMM (EPI: 0 none,1 relu,2 +res; OM: 0 lin) ------
template<int EPI, int OM>
__global__ __launch_bounds__(256, 2) void tgemm_kernel(const float* __restrict__ A,
                                                       const float* __restrict__ Bm,
                                                       const float* __restrict__ bias,
                                                       const float* __restrict__ res,
                                                       float* __restrict__ C,
                                                       __nv_bfloat16* __restrict__ Cb,
                                                       int M, int Nn, int K) {
    __shared__ uint32_t As[2][16][136];
    __shared__ uint32_t Bs[2][16][136];
    int tid = threadIdx.x;
    int lane = tid & 31;
    int wid = tid >> 5;
    int wm = (wid & 3) * 32;
    int wn = (wid >> 2) * 64;
    int g = lane >> 2, t4 = lane & 3;
    int m0 = blockIdx.y * 128;
    int n0 = blockIdx.x * 128;

    float acc[2][8][4];
    #pragma unroll
    for (int mt = 0; mt < 2; mt++)
        #pragma unroll
        for (int nt = 0; nt < 8; nt++)
            #pragma unroll
            for (int i = 0; i < 4; i++) acc[mt][nt][i] = 0.0f;

    GEMM_MAINLOOP(A, Bm, K, Nn, m0, n0, acc);

    #pragma unroll
    for (int mt = 0; mt < 2; mt++) {
        #pragma unroll
        for (int nt = 0; nt < 8; nt++) {
            int m = m0 + wm + mt * 16 + g;
            int n = n0 + wn + nt * 8 + 2 * t4;
            float bv0 = bias[n], bv1 = bias[n + 1];
            float v00 = acc[mt][nt][0] + bv0, v01 = acc[mt][nt][1] + bv1;
            float v10 = acc[mt][nt][2] + bv0, v11 = acc[mt][nt][3] + bv1;
            if (EPI == 1) {
                v00 = fmaxf(v00, 0.0f); v01 = fmaxf(v01, 0.0f);
                v10 = fmaxf(v10, 0.0f); v11 = fmaxf(v11, 0.0f);
            }
            if (EPI == 2) {
                float2 r0 = *(const float2*)(res + (size_t)m * Nn + n);
                float2 r1 = *(const float2*)(res + (size_t)(m + 8) * Nn + n);
                v00 += r0.x; v01 += r0.y; v10 += r1.x; v11 += r1.y;
            }
            float2 p0; p0.x = v00; p0.y = v01;
            float2 p1; p1.x = v10; p1.y = v11;
            *(float2*)(C + (size_t)m * Nn + n) = p0;
            *(float2*)(C + (size_t)(m + 8) * Nn + n) = p1;
        }
    }
}

// ---------------- fused QKV GEMM: blockIdx.x selects wq/wk/wv ---------------
// grid.x = 12: sel = x>>2 (0:q fp32, 1:k bf16, 2:v bf16), nblk = x&3.
__global__ __launch_bounds__(256, 2) void qkvgemm_kernel(const float* __restrict__ A,
                                                         const float* __restrict__ Wq,
                                                         const float* __restrict__ Wk,
                                                         const float* __restrict__ Wv,
                                                         const float* __restrict__ Bq,
                                                         const float* __restrict__ Bk,
                                                         const float* __restrict__ Bv,
                                                         float* __restrict__ Oq,
                                                         __nv_bfloat16* __restrict__ Ok,
                                                         __nv_bfloat16* __restrict__ Ov) {
    __shared__ uint32_t As[2][16][136];
    __shared__ uint32_t Bs[2][16][136];
    int tid = threadIdx.x;
    int lane = tid & 31;
    int wid = tid >> 5;
    int wm = (wid & 3) * 32;
    int wn = (wid >> 2) * 64;
    int g = lane >> 2, t4 = lane & 3;
    int sel = blockIdx.x >> 2;
    int m0 = blockIdx.y * 128;
    int n0 = (blockIdx.x & 3) * 128;

    const float* Bm   = sel == 0 ? Wq : (sel == 1 ? Wk : Wv);
    const float* bias = sel == 0 ? Bq : (sel == 1 ? Bk : Bv);

    float acc[2][8][4];
    #pragma unroll
    for (int mt = 0; mt < 2; mt++)
        #pragma unroll
        for (int nt = 0; nt < 8; nt++)
            #pragma unroll
            for (int i = 0; i < 4; i++) acc[mt][nt][i] = 0.0f;

    GEMM_MAINLOOP(A, Bm, DD, DD, m0, n0, acc);

    #pragma unroll
    for (int mt = 0; mt < 2; mt++) {
        #pragma unroll
        for (int nt = 0; nt < 8; nt++) {
            int m = m0 + wm + mt * 16 + g;
            int n = n0 + wn + nt * 8 + 2 * t4;
            float bv0 = bias[n], bv1 = bias[n + 1];
            float v00 = acc[mt][nt][0] + bv0, v01 = acc[mt][nt][1] + bv1;
            float v10 = acc[mt][nt][2] + bv0, v11 = acc[mt][nt][3] + bv1;
            int h = n >> 6, d = n & 63;
            int b0_ = m >> 11, nn0 = m & (NN - 1);
            int b1_ = (m + 8) >> 11, nn1 = (m + 8) & (NN - 1);
            size_t o0 = (((size_t)(b0_ * HH + h) * NN + nn0) << 6) + d;
            size_t o1 = (((size_t)(b1_ * HH + h) * NN + nn1) << 6) + d;
            if (sel == 0) {
                float2 p0; p0.x = v00; p0.y = v01;
                float2 p1; p1.x = v10; p1.y = v11;
                *(float2*)(Oq + o0) = p0;
                *(float2*)(Oq + o1) = p1;
            } else {
                __nv_bfloat16* dst = sel == 1 ? Ok : Ov;
                __nv_bfloat162 p0, p1;
                p0.x = __float2bfloat16(v00); p0.y = __float2bfloat16(v01);
                p1.x = __float2bfloat16(v10); p1.y = __float2bfloat16(v11);
                *(__nv_bfloat162*)&dst[o0] = p0;
                *(__nv_bfloat162*)&dst[o1] = p1;
            }
        }
    }
}

// ---------------- RoPE: q fp32, k bf16 -------------------------------------
__global__ __launch_bounds__(256) void rope_kernel(float* __restrict__ q,
                                                   __nv_bfloat16* __restrict__ k,
                                                   const int* __restrict__ positions) {
    int idx = blockIdx.x * blockDim.x + threadIdx.x;
    int pair = idx & 31;
    int r = idx >> 5;
    int n = r & (NN - 1);
    int bh = r >> 11;
    int b = bh >> 3;
    double pos = (double)positions[b * NN + n];
    double ang = pos * g_invf[pair];
    double kq  = rint(ang * 0.15915494309189535);
    float rr = (float)(ang - kq * 6.283185307179586);
    float c = __cosf(rr);
    float s = __sinf(rr);
    float* qp = q + (size_t)r * DK;
    __nv_bfloat16* kp = k + (size_t)r * DK;
    float q0 = qp[pair], q1 = qp[pair + 32];
    qp[pair]      = q0 * c - q1 * s;
    qp[pair + 32] = q1 * c + q0 * s;
    float k0 = __bfloat162float(kp[pair]);
    float k1 = __bfloat162float(kp[pair + 32]);
    kp[pair]      = __float2bfloat16(k0 * c - k1 * s);
    kp[pair + 32] = __float2bfloat16(k1 * c + k0 * s);
}

// ---------------- sparse gather attention: 4 threads per (b,h,row) ---------
__global__ __launch_bounds__(128) void attn_quad_kernel(const float* __restrict__ q,
                                                        const __nv_bfloat16* __restrict__ kb,
                                                        const __nv_bfloat16* __restrict__ vb,
                                                        float* __restrict__ out) {
    int bh = blockIdx.x;
    int b = bh >> 3, h = bh & 7;
    int tid = threadIdx.x;
    int ql = tid & 3;
    int row = blockIdx.y * 32 + (tid >> 2);
    int r = b * NN + row;
    unsigned qmask = 0xFu << ((tid & 31) & ~3);

    const unsigned short* list = g_idx + (size_t)r * NN;
    int n = g_cnt[r];

    const float* qr = q + ((size_t)bh * NN + row) * DK + ql * 16;
    float qreg[16];
    #pragma unroll
    for (int d = 0; d < 16; d += 4) {
        float4 t = *(const float4*)(qr + d);
        qreg[d] = t.x * 0.125f; qreg[d + 1] = t.y * 0.125f;
        qreg[d + 2] = t.z * 0.125f; qreg[d + 3] = t.w * 0.125f;
    }
    const __nv_bfloat16* kbase = kb + (size_t)bh * NN * DK + ql * 16;
    const __nv_bfloat16* vbase = vb + (size_t)bh * NN * DK + ql * 16;

    float o[16];
    #pragma unroll
    for (int d = 0; d < 16; d++) o[d] = 0.0f;
    float m = -INFINITY, l = 0.0f;

    int j = list[0];
    uint4 ku0 = *(const uint4*)(kbase + (size_t)j * DK);
    uint4 ku1 = *(const uint4*)(kbase + (size_t)j * DK + 8);

    for (int t = 0; t < n; t++) {
        float s0 = 0.f, s1 = 0.f;
        {
            float2 f;
            f = __bfloat1622float2(*(const __nv_bfloat162*)&ku0.x);
            s0 = fmaf(qreg[0], f.x, s0); s1 = fmaf(qreg[1], f.y, s1);
            f = __bfloat1622float2(*(const __nv_bfloat162*)&ku0.y);
            s0 = fmaf(qreg[2], f.x, s0); s1 = fmaf(qreg[3], f.y, s1);
            f = __bfloat1622float2(*(const __nv_bfloat162*)&ku0.z);
            s0 = fmaf(qreg[4], f.x, s0); s1 = fmaf(qreg[5], f.y, s1);
            f = __bfloat1622float2(*(const __nv_bfloat162*)&ku0.w);
            s0 = fmaf(qreg[6], f.x, s0); s1 = fmaf(qreg[7], f.y, s1);
            f = __bfloat1622float2(*(const __nv_bfloat162*)&ku1.x);
            s0 = fmaf(qreg[8], f.x, s0); s1 = fmaf(qreg[9], f.y, s1);
            f = __bfloat1622float2(*(const __nv_bfloat162*)&ku1.y);
            s0 = fmaf(qreg[10], f.x, s0); s1 = fmaf(qreg[11], f.y, s1);
            f = __bfloat1622float2(*(const __nv_bfloat162*)&ku1.z);
            s0 = fmaf(qreg[12], f.x, s0); s1 = fmaf(qreg[13], f.y, s1);
            f = __bfloat1622float2(*(const __nv_bfloat162*)&ku1.w);
            s0 = fmaf(qreg[14], f.x, s0); s1 = fmaf(qreg[15], f.y, s1);
        }
        uint4 vu0 = *(const uint4*)(vbase + (size_t)j * DK);
        uint4 vu1 = *(const uint4*)(vbase + (size_t)j * DK + 8);
        if (t + 1 < n) {
            j = list[t + 1];
            ku0 = *(const uint4*)(kbase + (size_t)j * DK);
            ku1 = *(const uint4*)(kbase + (size_t)j * DK + 8);
        }
        float s = s0 + s1;
        s += __shfl_xor_sync(qmask, s, 1);
        s += __shfl_xor_sync(qmask, s, 2);
        float newm = fmaxf(m, s);
        float alpha = __expf(m - newm);
        float p = __expf(s - newm);
        l = l * alpha + p;
        m = newm;
        {
            float2 f;
            f = __bfloat1622float2(*(const __nv_bfloat162*)&vu0.x);
            o[0] = fmaf(o[0], alpha, p * f.x); o[1] = fmaf(o[1], alpha, p * f.y);
            f = __bfloat1622float2(*(const __nv_bfloat162*)&vu0.y);
            o[2] = fmaf(o[2], alpha, p * f.x); o[3] = fmaf(o[3], alpha, p * f.y);
            f = __bfloat1622float2(*(const __nv_bfloat162*)&vu0.z);
            o[4] = fmaf(o[4], alpha, p * f.x); o[5] = fmaf(o[5], alpha, p * f.y);
            f = __bfloat1622float2(*(const __nv_bfloat162*)&vu0.w);
            o[6] = fmaf(o[6], alpha, p * f.x); o[7] = fmaf(o[7], alpha, p * f.y);
            f = __bfloat1622float2(*(const __nv_bfloat162*)&vu1.x);
            o[8] = fmaf(o[8], alpha, p * f.x); o[9] = fmaf(o[9], alpha, p * f.y);
            f = __bfloat1622float2(*(const __nv_bfloat162*)&vu1.y);
            o[10] = fmaf(o[10], alpha, p * f.x); o[11] = fmaf(o[11], alpha, p * f.y);
            f = __bfloat1622float2(*(const __nv_bfloat162*)&vu1.z);
            o[12] = fmaf(o[12], alpha, p * f.x); o[13] = fmaf(o[13], alpha, p * f.y);
            f = __bfloat1622float2(*(const __nv_bfloat162*)&vu1.w);
            o[14] = fmaf(o[14], alpha, p * f.x); o[15] = fmaf(o[15], alpha, p * f.y);
        }
    }

    float invl = 1.0f / l;
    float* orow = out + ((size_t)b * NN + row) * DD + h * DK + ql * 16;
    #pragma unroll
    for (int d = 0; d < 16; d += 4) {
        float4 t;
        t.x = o[d] * invl;     t.y = o[d + 1] * invl;
        t.z = o[d + 2] * invl; t.w = o[d + 3] * invl;
        *(float4*)(orow + d) = t;
    }
}

// ---------------- host launcher --------------------------------------------
extern "C" void kernel_launch(void* const* d_in, const int* in_sizes, int n_in,
                              void* d_out, int out_size) {
    const float* x        = (const float*)d_in[0];
    const unsigned char* o2o = (const unsigned char*)d_in[1];
    const int*   positions= (const int*)d_in[2];
    const float* wq = (const float*)d_in[3];  const float* bq = (const float*)d_in[4];
    const float* wk = (const float*)d_in[5];  const float* bk = (const float*)d_in[6];
    const float* wv = (const float*)d_in[7];  const float* bv = (const float*)d_in[8];
    const float* wo = (const float*)d_in[9];  const float* bo = (const float*)d_in[10];
    const float* ln1_g = (const float*)d_in[11]; const float* ln1_b = (const float*)d_in[12];
    const float* ln2_g = (const float*)d_in[13]; const float* ln2_b = (const float*)d_in[14];
    const float* w1 = (const float*)d_in[15]; const float* b1 = (const float*)d_in[16];
    const float* w2 = (const float*)d_in[17]; const float* b2 = (const float*)d_in[18];
    float* out = (float*)d_out;

    float *p_xn, *p_q, *p_att, *p_x2, *p_h, *p_act;
    __nv_bfloat16 *p_kb, *p_vb;
    cudaGetSymbolAddress((void**)&p_xn,  g_xn);
    cudaGetSymbolAddress((void**)&p_q,   g_q);
    cudaGetSymbolAddress((void**)&p_kb,  g_kb);
    cudaGetSymbolAddress((void**)&p_vb,  g_vb);
    cudaGetSymbolAddress((void**)&p_att, g_att);
    cudaGetSymbolAddress((void**)&p_x2,  g_x2);
    cudaGetSymbolAddress((void**)&p_h,   g_h);
    cudaGetSymbolAddress((void**)&p_act, g_act);

    // 0) probes / tables / index lists
    probe_mask_kernel<<<1, 256>>>(o2o);
    rope_init_kernel<<<1, 32>>>();
    build_idx_kernel<<<MROWS / 8, 256>>>(o2o);

    // 1) LN1
    ln_kernel<<<MROWS, 128>>>(x, ln1_g, ln1_b, p_xn);

    // 2) fused Q/K/V projections -> (B,H,N,DK); Q fp32, K/V bf16
    dim3 gqkv(12, MROWS / 128);
    qkvgemm_kernel<<<gqkv, 256>>>(p_xn, wq, wk, wv, bq, bk, bv, p_q, p_kb, p_vb);

    // 3) RoPE on q,k
    rope_kernel<<<(BB * HH * NN * 32) / 256, 256>>>(p_q, p_kb, positions);

    // 4) sparse gather attention (quad per row) -> (B,N,D)
    dim3 gatt(BB * HH, NN / 32);
    attn_quad_kernel<<<gatt, 128>>>(p_q, p_kb, p_vb, p_att);

    // 5) output projection + residual
    dim3 gproj(DD / 128, MROWS / 128);
    tgemm_kernel<2, 0><<<gproj, 256>>>(p_att, wo, bo, x, p_x2, nullptr, MROWS, DD, DD);

    // 6) LN2
    ln_kernel<<<MROWS, 128>>>(p_x2, ln2_g, ln2_b, p_h);

    // 7) FFN up + relu
    dim3 gffn1(FFN / 128, MROWS / 128);
    tgemm_kernel<1, 0><<<gffn1, 256>>>(p_h, w1, b1, nullptr, p_act, nullptr, MROWS, FFN, DD);

    // 8) FFN down + residual -> out
    tgemm_kernel<2, 0><<<gproj, 256>>>(p_act, w2, b2, p_x2, out, nullptr, MROWS, DD, FFN);
}

// round 14
// speedup vs baseline: 1.0799x; 1.0799x over previous
#include <cuda_runtime.h>
#include <cuda_bf16.h>
#include <math.h>
#include <stdint.h>

// Problem constants
#define BB 4
#define NN 2048
#define DD 512
#define HH 8
#define DK 64
#define FFN 2048
#define MROWS (BB*NN)          // 8192

// ---------------- scratch (device globals; allocation-free) ----------------
__device__ float g_xn [MROWS*DD];
__device__ float g_q  [MROWS*DD];            // fp32 (B,H,N,DK)
__device__ __nv_bfloat16 g_kb[MROWS*DD];     // bf16 (B,H,N,DK)
__device__ __nv_bfloat16 g_vb[MROWS*DD];     // bf16 (B,H,N,DK)
__device__ float g_att[MROWS*DD];            // (B,N,D)
__device__ float g_x2 [MROWS*DD];
__device__ float g_h  [MROWS*DD];
__device__ float g_act[MROWS*FFN];
__device__ unsigned short g_idx[(size_t)MROWS*NN];
__device__ int    g_cnt[MROWS];
__device__ int    g_maskmode;
__device__ double g_invf[32];

// ---------------- mask dtype probe -----------------------------------------
__global__ void probe_mask_kernel(const unsigned char* __restrict__ m) {
    __shared__ int ok;
    if (threadIdx.x == 0) ok = 1;
    __syncthreads();
    int bad = 0;
    for (int i = threadIdx.x; i < NN; i += blockDim.x)
        if (m[(size_t)i * (NN + 1)] == 0) bad = 1;
    if (bad) atomicAnd(&ok, 0);
    __syncthreads();
    if (threadIdx.x == 0) g_maskmode = ok ? 0 : 1;
}

// ---------------- build compact index lists (1 warp per query row) ---------
__global__ __launch_bounds__(256) void build_idx_kernel(const unsigned char* __restrict__ mask) {
    int warp = threadIdx.x >> 5;
    int lane = threadIdx.x & 31;
    int row = blockIdx.x * 8 + warp;
    if (row >= MROWS) return;
    int mode = g_maskmode;
    const unsigned char* m8 = mask + (size_t)row * NN;
    const unsigned int* m32 = ((const unsigned int*)mask) + (size_t)row * NN;
    unsigned short* dst = g_idx + (size_t)row * NN;
    int cnt = 0;
    for (int j0 = 0; j0 < NN; j0 += 32) {
        int on = mode == 0 ? (m8[j0 + lane] != 0) : (m32[j0 + lane] != 0u);
        unsigned bal = __ballot_sync(0xffffffffu, on);
        int pre = __popc(bal & ((1u << lane) - 1u));
        if (on) dst[cnt + pre] = (unsigned short)(j0 + lane);
        cnt += __popc(bal);
    }
    if (lane == 0) g_cnt[row] = cnt;
}

// ---------------- RoPE frequency table -------------------------------------
__global__ void rope_init_kernel() {
    int i = threadIdx.x;
    if (i < 32)
        g_invf[i] = exp2(-((double)(2 * i) / 64.0) * 13.287712379549448);
}

// ---------------- LayerNorm -------------------------------------------------
__global__ __launch_bounds__(128) void ln_kernel(const float* __restrict__ x,
                                                 const float* __restrict__ g,
                                                 const float* __restrict__ b,
                                                 float* __restrict__ out) {
    int row = blockIdx.x;
    int t = threadIdx.x;
    const float4* xr = (const float4*)(x + (size_t)row * DD);
    float4 v = xr[t];
    float s  = v.x + v.y + v.z + v.w;
    float s2 = fmaf(v.x, v.x, fmaf(v.y, v.y, fmaf(v.z, v.z, v.w * v.w)));
    #pragma unroll
    for (int off = 16; off > 0; off >>= 1) {
        s  += __shfl_xor_sync(0xffffffffu, s,  off);
        s2 += __shfl_xor_sync(0xffffffffu, s2, off);
    }
    __shared__ float sh[8];
    int w = t >> 5;
    if ((t & 31) == 0) { sh[w] = s; sh[4 + w] = s2; }
    __syncthreads();
    float ts  = sh[0] + sh[1] + sh[2] + sh[3];
    float ts2 = sh[4] + sh[5] + sh[6] + sh[7];
    float mean = ts * (1.0f / DD);
    float var  = ts2 * (1.0f / DD) - mean * mean;
    float inv  = rsqrtf(var + 1e-5f);
    float4 gv = ((const float4*)g)[t];
    float4 bv = ((const float4*)b)[t];
    float4 o;
    o.x = (v.x - mean) * inv * gv.x + bv.x;
    o.y = (v.y - mean) * inv * gv.y + bv.y;
    o.z = (v.z - mean) * inv * gv.z + bv.z;
    o.w = (v.w - mean) * inv * gv.w + bv.w;
    ((float4*)(out + (size_t)row * DD))[t] = o;
}

// ---------------- mma helper ------------------------------------------------
__device__ __forceinline__ void mma_tf32(float* d, const uint32_t* a, const uint32_t* b) {
    asm volatile("mma.sync.aligned.m16n8k8.row.col.f32.tf32.tf32.f32 "
                 "{%0,%1,%2,%3}, {%4,%5,%6,%7}, {%8,%9}, {%0,%1,%2,%3};"
                 : "+f"(d[0]), "+f"(d[1]), "+f"(d[2]), "+f"(d[3])
                 : "r"(a[0]), "r"(a[1]), "r"(a[2]), "r"(a[3]),
                   "r"(b[0]), "r"(b[1]));
}
__device__ __forceinline__ uint32_t smem_u32(const void* p) {
    uint32_t a;
    asm("{ .reg .u64 t; cvta.to.shared.u64 t, %1; cvt.u32.u64 %0, t; }" : "=r"(a) : "l"(p));
    return a;
}
__device__ __forceinline__ void cp16(uint32_t dst, const void* src) {
    asm volatile("cp.async.cg.shared.global [%0], [%1], 16;" :: "r"(dst), "l"(src) : "memory");
}

// ============ TF32 GEMM, cp.async 3-stage pipeline, raw-fp32-as-tf32 ========
// A tile in SMEM: [128 m][16 k], row stride 20 words (conflict-free frags).
// B tile in SMEM: [16 k][128 n], row stride 136 words.
// EPI: 0 none, 1 relu, 2 +residual.  OM: 0 fp32 linear, 1 fp32 scatter, 2 bf16 scatter.
#define GK_ASZ   10240                 // 128*80 bytes
#define GK_BSZ   8704                  // 16*544 bytes
#define GK_STAGE (GK_ASZ + GK_BSZ)     // 18944
#define GK_SMEM  (3 * GK_STAGE)        // 56832

template<int EPI, int OM>
__global__ __launch_bounds__(256, 2) void tgemm_kernel(const float* __restrict__ A,
                                                       const float* __restrict__ Bm,
                                                       const float* __restrict__ bias,
                                                       const float* __restrict__ res,
                                                       float* __restrict__ C,
                                                       __nv_bfloat16* __restrict__ Cb,
                                                       int M, int Nn, int K) {
    extern __shared__ char dsm[];
    uint32_t sb = smem_u32(dsm);
    int tid = threadIdx.x;
    int lane = tid & 31;
    int wid = tid >> 5;
    int wm = (wid & 3) * 32;
    int wn = (wid >> 2) * 64;
    int g = lane >> 2, t4 = lane & 3;
    int m0 = blockIdx.y * 128;
    int n0 = blockIdx.x * 128;

    // cp.async mappings (all sizes exact multiples; no predication needed)
    int arow = tid >> 1;               // A row 0..127
    int aseg = (tid & 1) * 2;          // 2 of 4 16B segs per row
    int brow = tid >> 4;               // B k-row 0..15
    int bseg = (tid & 15) * 2;         // 2 of 32 16B segs per row
    const char* aSrc = (const char*)(A + (size_t)(m0 + arow) * K + aseg * 4);
    const char* bSrc = (const char*)(Bm + (size_t)brow * Nn + n0 + bseg * 4);
    uint32_t aDst = sb + (uint32_t)(arow * 80 + aseg * 16);
    uint32_t bDst = sb + GK_ASZ + (uint32_t)(brow * 544 + bseg * 16);
    size_t bAdv = (size_t)16 * Nn * 4;   // bytes per 16-k advance (B)
    // A advances 64 bytes per 16-k tile

    int NT = K >> 4;                   // number of 16-k tiles

    #pragma unroll
    for (int s = 0; s < 2; s++) {      // prologue: stages 0,1
        uint32_t off = (uint32_t)s * GK_STAGE;
        cp16(aDst + off,      aSrc + (size_t)s * 64);
        cp16(aDst + off + 16, aSrc + (size_t)s * 64 + 16);
        cp16(bDst + off,      bSrc + (size_t)s * bAdv);
        cp16(bDst + off + 16, bSrc + (size_t)s * bAdv + 16);
        asm volatile("cp.async.commit_group;" ::: "memory");
    }

    float acc[2][8][4];
    #pragma unroll
    for (int mt = 0; mt < 2; mt++)
        #pragma unroll
        for (int nt = 0; nt < 8; nt++)
            #pragma unroll
            for (int i = 0; i < 4; i++) acc[mt][nt][i] = 0.0f;

    for (int c = 0; c < NT; c++) {
        asm volatile("cp.async.wait_group 1;" ::: "memory");
        __syncthreads();
        int cn = c + 2;
        if (cn < NT) {                 // refill stage (c+2)%3 == (c-1)%3 (reads done)
            uint32_t off = (uint32_t)(cn % 3) * GK_STAGE;
            cp16(aDst + off,      aSrc + (size_t)cn * 64);
            cp16(aDst + off + 16, aSrc + (size_t)cn * 64 + 16);
            cp16(bDst + off,      bSrc + (size_t)cn * bAdv);
            cp16(bDst + off + 16, bSrc + (size_t)cn * bAdv + 16);
        }
        asm volatile("cp.async.commit_group;" ::: "memory");

        const uint32_t* Asm = (const uint32_t*)(dsm + (c % 3) * GK_STAGE);
        const uint32_t* Bsm = (const uint32_t*)(dsm + (c % 3) * GK_STAGE + GK_ASZ);
        #pragma unroll
        for (int kk = 0; kk < 16; kk += 8) {
            uint32_t a[2][4];
            #pragma unroll
            for (int mt = 0; mt < 2; mt++) {
                int m = wm + mt * 16 + g;
                a[mt][0] = Asm[m * 20 + kk + t4];
                a[mt][1] = Asm[(m + 8) * 20 + kk + t4];
                a[mt][2] = Asm[m * 20 + kk + t4 + 4];
                a[mt][3] = Asm[(m + 8) * 20 + kk + t4 + 4];
            }
            uint32_t b[8][2];
            #pragma unroll
            for (int nt = 0; nt < 8; nt++) {
                int n = wn + nt * 8 + g;
                b[nt][0] = Bsm[(kk + t4) * 136 + n];
                b[nt][1] = Bsm[(kk + t4 + 4) * 136 + n];
            }
            #pragma unroll
            for (int mt = 0; mt < 2; mt++)
                #pragma unroll
                for (int nt = 0; nt < 8; nt++)
                    mma_tf32(acc[mt][nt], a[mt], b[nt]);
        }
    }

    // ---------------- epilogue ----------------
    #pragma unroll
    for (int mt = 0; mt < 2; mt++) {
        #pragma unroll
        for (int nt = 0; nt < 8; nt++) {
            int m = m0 + wm + mt * 16 + g;
            int n = n0 + wn + nt * 8 + 2 * t4;
            float bv0 = bias[n], bv1 = bias[n + 1];
            float v00 = acc[mt][nt][0] + bv0, v01 = acc[mt][nt][1] + bv1;
            float v10 = acc[mt][nt][2] + bv0, v11 = acc[mt][nt][3] + bv1;
            if (EPI == 1) {
                v00 = fmaxf(v00, 0.0f); v01 = fmaxf(v01, 0.0f);
                v10 = fmaxf(v10, 0.0f); v11 = fmaxf(v11, 0.0f);
            }
            if (EPI == 2) {
                float2 r0 = *(const float2*)(res + (size_t)m * Nn + n);
                float2 r1 = *(const float2*)(res + (size_t)(m + 8) * Nn + n);
                v00 += r0.x; v01 += r0.y; v10 += r1.x; v11 += r1.y;
            }
            if (OM == 0) {
                float2 p0; p0.x = v00; p0.y = v01;
                float2 p1; p1.x = v10; p1.y = v11;
                *(float2*)(C + (size_t)m * Nn + n) = p0;
                *(float2*)(C + (size_t)(m + 8) * Nn + n) = p1;
            } else {
                int h = n >> 6, d = n & 63;
                int b0_ = m >> 11, nn0 = m & (NN - 1);
                int b1_ = (m + 8) >> 11, nn1 = (m + 8) & (NN - 1);
                size_t o0 = (((size_t)(b0_ * HH + h) * NN + nn0) << 6) + d;
                size_t o1 = (((size_t)(b1_ * HH + h) * NN + nn1) << 6) + d;
                if (OM == 1) {
                    float2 p0; p0.x = v00; p0.y = v01;
                    float2 p1; p1.x = v10; p1.y = v11;
                    *(float2*)(C + o0) = p0;
                    *(float2*)(C + o1) = p1;
                } else {
                    __nv_bfloat162 p0, p1;
                    p0.x = __float2bfloat16(v00); p0.y = __float2bfloat16(v01);
                    p1.x = __float2bfloat16(v10); p1.y = __float2bfloat16(v11);
                    *(__nv_bfloat162*)&Cb[o0] = p0;
                    *(__nv_bfloat162*)&Cb[o1] = p1;
                }
            }
        }
    }
}

// ---------------- RoPE: q fp32, k bf16 -------------------------------------
__global__ __launch_bounds__(256) void rope_kernel(float* __restrict__ q,
                                                   __nv_bfloat16* __restrict__ k,
                                                   const int* __restrict__ positions) {
    int idx = blockIdx.x * blockDim.x + threadIdx.x;
    int pair = idx & 31;
    int r = idx >> 5;
    int n = r & (NN - 1);
    int bh = r >> 11;
    int b = bh >> 3;
    double pos = (double)positions[b * NN + n];
    double ang = pos * g_invf[pair];
    double kq  = rint(ang * 0.15915494309189535);
    float rr = (float)(ang - kq * 6.283185307179586);
    float c = __cosf(rr);
    float s = __sinf(rr);
    float* qp = q + (size_t)r * DK;
    __nv_bfloat16* kp = k + (size_t)r * DK;
    float q0 = qp[pair], q1 = qp[pair + 32];
    qp[pair]      = q0 * c - q1 * s;
    qp[pair + 32] = q1 * c + q0 * s;
    float k0 = __bfloat162float(kp[pair]);
    float k1 = __bfloat162float(kp[pair + 32]);
    kp[pair]      = __float2bfloat16(k0 * c - k1 * s);
    kp[pair + 32] = __float2bfloat16(k1 * c + k0 * s);
}

// ---------------- sparse gather attention: 4 threads per (b,h,row) ---------
__global__ __launch_bounds__(128) void attn_quad_kernel(const float* __restrict__ q,
                                                        const __nv_bfloat16* __restrict__ kb,
                                                        const __nv_bfloat16* __restrict__ vb,
                                                        float* __restrict__ out) {
    int bh = blockIdx.x;
    int b = bh >> 3, h = bh & 7;
    int tid = threadIdx.x;
    int ql = tid & 3;
    int row = blockIdx.y * 32 + (tid >> 2);
    int r = b * NN + row;
    unsigned qmask = 0xFu << ((tid & 31) & ~3);

    const unsigned short* list = g_idx + (size_t)r * NN;
    int n = g_cnt[r];

    const float* qr = q + ((size_t)bh * NN + row) * DK + ql * 16;
    float qreg[16];
    #pragma unroll
    for (int d = 0; d < 16; d += 4) {
        float4 t = *(const float4*)(qr + d);
        qreg[d] = t.x * 0.125f; qreg[d + 1] = t.y * 0.125f;
        qreg[d + 2] = t.z * 0.125f; qreg[d + 3] = t.w * 0.125f;
    }
    const __nv_bfloat16* kbase = kb + (size_t)bh * NN * DK + ql * 16;
    const __nv_bfloat16* vbase = vb + (size_t)bh * NN * DK + ql * 16;

    float o[16];
    #pragma unroll
    for (int d = 0; d < 16; d++) o[d] = 0.0f;
    float m = -INFINITY, l = 0.0f;

    int j = list[0];
    uint4 ku0 = *(const uint4*)(kbase + (size_t)j * DK);
    uint4 ku1 = *(const uint4*)(kbase + (size_t)j * DK + 8);

    for (int t = 0; t < n; t++) {
        float s0 = 0.f, s1 = 0.f;
        {
            float2 f;
            f = __bfloat1622float2(*(const __nv_bfloat162*)&ku0.x);
            s0 = fmaf(qreg[0], f.x, s0); s1 = fmaf(qreg[1], f.y, s1);
            f = __bfloat1622float2(*(const __nv_bfloat162*)&ku0.y);
            s0 = fmaf(qreg[2], f.x, s0); s1 = fmaf(qreg[3], f.y, s1);
            f = __bfloat1622float2(*(const __nv_bfloat162*)&ku0.z);
            s0 = fmaf(qreg[4], f.x, s0); s1 = fmaf(qreg[5], f.y, s1);
            f = __bfloat1622float2(*(const __nv_bfloat162*)&ku0.w);
            s0 = fmaf(qreg[6], f.x, s0); s1 = fmaf(qreg[7], f.y, s1);
            f = __bfloat1622float2(*(const __nv_bfloat162*)&ku1.x);
            s0 = fmaf(qreg[8], f.x, s0); s1 = fmaf(qreg[9], f.y, s1);
            f = __bfloat1622float2(*(const __nv_bfloat162*)&ku1.y);
            s0 = fmaf(qreg[10], f.x, s0); s1 = fmaf(qreg[11], f.y, s1);
            f = __bfloat1622float2(*(const __nv_bfloat162*)&ku1.z);
            s0 = fmaf(qreg[12], f.x, s0); s1 = fmaf(qreg[13], f.y, s1);
            f = __bfloat1622float2(*(const __nv_bfloat162*)&ku1.w);
            s0 = fmaf(qreg[14], f.x, s0); s1 = fmaf(qreg[15], f.y, s1);
        }
        uint4 vu0 = *(const uint4*)(vbase + (size_t)j * DK);
        uint4 vu1 = *(const uint4*)(vbase + (size_t)j * DK + 8);
        if (t + 1 < n) {
            j = list[t + 1];
            ku0 = *(const uint4*)(kbase + (size_t)j * DK);
            ku1 = *(const uint4*)(kbase + (size_t)j * DK + 8);
        }
        float s = s0 + s1;
        s += __shfl_xor_sync(qmask, s, 1);
        s += __shfl_xor_sync(qmask, s, 2);
        float newm = fmaxf(m, s);
        float alpha = __expf(m - newm);
        float p = __expf(s - newm);
        l = l * alpha + p;
        m = newm;
        {
            float2 f;
            f = __bfloat1622float2(*(const __nv_bfloat162*)&vu0.x);
            o[0] = fmaf(o[0], alpha, p * f.x); o[1] = fmaf(o[1], alpha, p * f.y);
            f = __bfloat1622float2(*(const __nv_bfloat162*)&vu0.y);
            o[2] = fmaf(o[2], alpha, p * f.x); o[3] = fmaf(o[3], alpha, p * f.y);
            f = __bfloat1622float2(*(const __nv_bfloat162*)&vu0.z);
            o[4] = fmaf(o[4], alpha, p * f.x); o[5] = fmaf(o[5], alpha, p * f.y);
            f = __bfloat1622float2(*(const __nv_bfloat162*)&vu0.w);
            o[6] = fmaf(o[6], alpha, p * f.x); o[7] = fmaf(o[7], alpha, p * f.y);
            f = __bfloat1622float2(*(const __nv_bfloat162*)&vu1.x);
            o[8] = fmaf(o[8], alpha, p * f.x); o[9] = fmaf(o[9], alpha, p * f.y);
            f = __bfloat1622float2(*(const __nv_bfloat162*)&vu1.y);
            o[10] = fmaf(o[10], alpha, p * f.x); o[11] = fmaf(o[11], alpha, p * f.y);
            f = __bfloat1622float2(*(const __nv_bfloat162*)&vu1.z);
            o[12] = fmaf(o[12], alpha, p * f.x); o[13] = fmaf(o[13], alpha, p * f.y);
            f = __bfloat1622float2(*(const __nv_bfloat162*)&vu1.w);
            o[14] = fmaf(o[14], alpha, p * f.x); o[15] = fmaf(o[15], alpha, p * f.y);
        }
    }

    float invl = 1.0f / l;
    float* orow = out + ((size_t)b * NN + row) * DD + h * DK + ql * 16;
    #pragma unroll
    for (int d = 0; d < 16; d += 4) {
        float4 t;
        t.x = o[d] * invl;     t.y = o[d + 1] * invl;
        t.z = o[d + 2] * invl; t.w = o[d + 3] * invl;
        *(float4*)(orow + d) = t;
    }
}

// ---------------- host launcher --------------------------------------------
extern "C" void kernel_launch(void* const* d_in, const int* in_sizes, int n_in,
                              void* d_out, int out_size) {
    const float* x        = (const float*)d_in[0];
    const unsigned char* o2o = (const unsigned char*)d_in[1];
    const int*   positions= (const int*)d_in[2];
    const float* wq = (const float*)d_in[3];  const float* bq = (const float*)d_in[4];
    const float* wk = (const float*)d_in[5];  const float* bk = (const float*)d_in[6];
    const float* wv = (const float*)d_in[7];  const float* bv = (const float*)d_in[8];
    const float* wo = (const float*)d_in[9];  const float* bo = (const float*)d_in[10];
    const float* ln1_g = (const float*)d_in[11]; const float* ln1_b = (const float*)d_in[12];
    const float* ln2_g = (const float*)d_in[13]; const float* ln2_b = (const float*)d_in[14];
    const float* w1 = (const float*)d_in[15]; const float* b1 = (const float*)d_in[16];
    const float* w2 = (const float*)d_in[17]; const float* b2 = (const float*)d_in[18];
    float* out = (float*)d_out;

    float *p_xn, *p_q, *p_att, *p_x2, *p_h, *p_act;
    __nv_bfloat16 *p_kb, *p_vb;
    cudaGetSymbolAddress((void**)&p_xn,  g_xn);
    cudaGetSymbolAddress((void**)&p_q,   g_q);
    cudaGetSymbolAddress((void**)&p_kb,  g_kb);
    cudaGetSymbolAddress((void**)&p_vb,  g_vb);
    cudaGetSymbolAddress((void**)&p_att, g_att);
    cudaGetSymbolAddress((void**)&p_x2,  g_x2);
    cudaGetSymbolAddress((void**)&p_h,   g_h);
    cudaGetSymbolAddress((void**)&p_act, g_act);

    cudaFuncSetAttribute(tgemm_kernel<0,1>, cudaFuncAttributeMaxDynamicSharedMemorySize, GK_SMEM);
    cudaFuncSetAttribute(tgemm_kernel<0,2>, cudaFuncAttributeMaxDynamicSharedMemorySize, GK_SMEM);
    cudaFuncSetAttribute(tgemm_kernel<2,0>, cudaFuncAttributeMaxDynamicSharedMemorySize, GK_SMEM);
    cudaFuncSetAttribute(tgemm_kernel<1,0>, cudaFuncAttributeMaxDynamicSharedMemorySize, GK_SMEM);

    // 0) probes / tables / index lists
    probe_mask_kernel<<<1, 256>>>(o2o);
    rope_init_kernel<<<1, 32>>>();
    build_idx_kernel<<<MROWS / 8, 256>>>(o2o);

    // 1) LN1
    ln_kernel<<<MROWS, 128>>>(x, ln1_g, ln1_b, p_xn);

    // 2) Q/K/V projections -> (B,H,N,DK); Q fp32, K/V bf16
    dim3 gproj(DD / 128, MROWS / 128);
    tgemm_kernel<0,1><<<gproj, 256, GK_SMEM>>>(p_xn, wq, bq, nullptr, p_q, nullptr, MROWS, DD, DD);
    tgemm_kernel<0,2><<<gproj, 256, GK_SMEM>>>(p_xn, wk, bk, nullptr, nullptr, p_kb, MROWS, DD, DD);
    tgemm_kernel<0,2><<<gproj, 256, GK_SMEM>>>(p_xn, wv, bv, nullptr, nullptr, p_vb, MROWS, DD, DD);

    // 3) RoPE on q,k
    rope_kernel<<<(BB * HH * NN * 32) / 256, 256>>>(p_q, p_kb, positions);

    // 4) sparse gather attention (quad per row) -> (B,N,D)
    dim3 gatt(BB * HH, NN / 32);
    attn_quad_kernel<<<gatt, 128>>>(p_q, p_kb, p_vb, p_att);

    // 5) output projection + residual
    tgemm_kernel<2,0><<<gproj, 256, GK_SMEM>>>(p_att, wo, bo, x, p_x2, nullptr, MROWS, DD, DD);

    // 6) LN2
    ln_kernel<<<MROWS, 128>>>(p_x2, ln2_g, ln2_b, p_h);

    // 7) FFN up + relu
    dim3 gffn1(FFN / 128, MROWS / 128);
    tgemm_kernel<1,0><<<gffn1, 256, GK_SMEM>>>(p_h, w1, b1, nullptr, p_act, nullptr, MROWS, FFN, DD);

    // 8) FFN down + residual -> out
    tgemm_kernel<2,0><<<gproj, 256, GK_SMEM>>>(p_act, w2, b2, p_x2, out, nullptr, MROWS, DD, FFN);
}